// round 6
// baseline (speedup 1.0000x reference)
#include <cuda_runtime.h>
#include <cuda_bf16.h>
#include <cstdint>
#include <math.h>

#define S_LEN 4096
#define NB 8
#define DIN 256
#define DH 512
#define NCH (NB * DH)          /* 4096 channels */
#define MROWS (NB * S_LEN)     /* 32768 gemm rows */
#define NTOT (4 * DH)          /* 2048 concat N */

#define TSEG 64
#define NSEG (S_LEN / TSEG)

/* Gate scratch, time-major [S][B*H]. 64 MB each. */
__device__ float g_gi[S_LEN * NCH];
__device__ float g_gf[S_LEN * NCH];
__device__ float g_go[S_LEN * NCH];
__device__ float g_gz[S_LEN * NCH];

/* Segment aggregates / starts */
__device__ float g_A [NSEG * NCH];
__device__ float g_Bc[NSEG * NCH];
__device__ float g_Bn[NSEG * NCH];
__device__ float g_Cs[NSEG * NCH];
__device__ float g_Ns[NSEG * NCH];

/* bf16 split operands */
__device__ __nv_bfloat16 g_xhi[(size_t)MROWS * DIN];
__device__ __nv_bfloat16 g_xlo[(size_t)MROWS * DIN];
__device__ __nv_bfloat16 g_wthi[(size_t)NTOT * DIN];   /* transposed: [n_global][k] */
__device__ __nv_bfloat16 g_wtlo[(size_t)NTOT * DIN];

/* ------------------------------------------------------------------ */
__device__ __forceinline__ uint32_t smem_u32(const void* p) {
    uint32_t a;
    asm("{ .reg .u64 t; cvta.to.shared.u64 t, %1; cvt.u32.u64 %0, t; }" : "=r"(a) : "l"(p));
    return a;
}
__device__ __forceinline__ void cp_async16(uint32_t saddr, const void* g) {
    asm volatile("cp.async.cg.shared.global [%0], [%1], 16;" :: "r"(saddr), "l"(g));
}
__device__ __forceinline__ void cp_commit() {
    asm volatile("cp.async.commit_group;");
}
__device__ __forceinline__ void cp_wait0() {
    asm volatile("cp.async.wait_group 0;");
}
__device__ __forceinline__ void ldm_x4(uint32_t& r0, uint32_t& r1, uint32_t& r2, uint32_t& r3,
                                       uint32_t addr) {
    asm volatile("ldmatrix.sync.aligned.m8n8.x4.shared.b16 {%0,%1,%2,%3}, [%4];"
                 : "=r"(r0), "=r"(r1), "=r"(r2), "=r"(r3) : "r"(addr));
}
__device__ __forceinline__ void mma16816(float* c, const uint32_t* a, const uint32_t* b) {
    asm volatile(
        "mma.sync.aligned.m16n8k16.row.col.f32.bf16.bf16.f32 "
        "{%0,%1,%2,%3}, {%4,%5,%6,%7}, {%8,%9}, {%0,%1,%2,%3};"
        : "+f"(c[0]), "+f"(c[1]), "+f"(c[2]), "+f"(c[3])
        : "r"(a[0]), "r"(a[1]), "r"(a[2]), "r"(a[3]), "r"(b[0]), "r"(b[1]));
}

/* ------------------------------------------------------------------ */
/* Conversion kernels                                                  */
/* ------------------------------------------------------------------ */
__global__ __launch_bounds__(256) void convert_x(const float* __restrict__ x)
{
    size_t i = ((size_t)blockIdx.x * 256 + threadIdx.x) * 4;
    float4 v = *(const float4*)(x + i);
    float vv[4] = {v.x, v.y, v.z, v.w};
#pragma unroll
    for (int j = 0; j < 4; j++) {
        __nv_bfloat16 h = __float2bfloat16_rn(vv[j]);
        g_xhi[i + j] = h;
        g_xlo[i + j] = __float2bfloat16_rn(vv[j] - __bfloat162float(h));
    }
}

__global__ void convert_w(const float* __restrict__ Wi, const float* __restrict__ Wf,
                          const float* __restrict__ Wo, const float* __restrict__ Wz)
{
    const float* W = (blockIdx.z == 0) ? Wi : (blockIdx.z == 1) ? Wf
                   : (blockIdx.z == 2) ? Wo : Wz;
    __shared__ float t[32][33];
    int k0 = blockIdx.x * 32, n0 = blockIdx.y * 32;
    int tx = threadIdx.x, ty = threadIdx.y;    /* (32,8) */
#pragma unroll
    for (int j = 0; j < 4; j++)
        t[ty * 4 + j][tx] = W[(size_t)(k0 + ty * 4 + j) * DH + n0 + tx];
    __syncthreads();
#pragma unroll
    for (int j = 0; j < 4; j++) {
        float v = t[tx][ty * 4 + j];           /* k = k0+tx, n = n0+ty*4+j */
        size_t o = (size_t)(blockIdx.z * DH + n0 + ty * 4 + j) * DIN + k0 + tx;
        __nv_bfloat16 h = __float2bfloat16_rn(v);
        g_wthi[o] = h;
        g_wtlo[o] = __float2bfloat16_rn(v - __bfloat162float(h));
    }
}

/* ------------------------------------------------------------------ */
/* HMMA GEMM, 3-term bf16 split with shared operand quads.             */
/* BM=128 BN=128 BK=32, 8 warps, warp tile 64x32.                      */
/* Per k-chunk: load {A_hi, A_lo, B_hi, B_lo} once, run 3 term passes. */
/* ------------------------------------------------------------------ */
#define LDS 40                         /* smem row stride in halves */
#define TILE_B (128 * LDS * 2)         /* 10240 B per tile */
#define BUF_B  (4 * TILE_B)            /* 40960 B per stage buffer */
#define GEMM_SMEM (2 * BUF_B)          /* 81920 B */
#define NKC 8                          /* 8 k-chunks of 32 */

__global__ __launch_bounds__(256) void gemm_hmma(
    const float* __restrict__ bi, const float* __restrict__ bfp,
    const float* __restrict__ bo, const float* __restrict__ bz)
{
    extern __shared__ __align__(16) char smem[];

    const int tid  = threadIdx.x;
    const int lane = tid & 31;
    const int w    = tid >> 5;
    const int wm   = w & 1;          /* warp m index (0..1)  -> 64 rows  */
    const int wn   = w >> 1;         /* warp n index (0..3)  -> 32 cols  */

    const int m0 = blockIdx.y * 128;
    const int n0 = blockIdx.x * 128; /* global concat-n */

    const uint32_t sb = smem_u32(smem);

    float acc[4][4][4];
#pragma unroll
    for (int i = 0; i < 4; i++)
#pragma unroll
        for (int j = 0; j < 4; j++)
#pragma unroll
            for (int e = 0; e < 4; e++) acc[i][j][e] = 0.f;

    /* ldmatrix lane address components */
    const uint32_t aRow = (lane & 15);
    const uint32_t aKof = (lane >> 4) * 8;
    const uint32_t bRow = (lane & 7) + ((lane >> 4) << 3);
    const uint32_t bKof = ((lane >> 3) & 1) * 8;

    /* per-thread copy mapping: chunk c in [0,512): row=c>>2, k16=c&3 */
    const int r0row = tid >> 2;
    const int r0k16 = tid & 3;
    const int r1row = (tid + 256) >> 2;
    const int r1k16 = tid & 3;   /* (tid+256)&3 == tid&3 */

    auto issue_stage = [&](int kc, int buf) {
        const int k0 = kc * 32;
        const __nv_bfloat16* srcs[4] = {
            g_xhi  + (size_t)m0 * DIN, g_xlo  + (size_t)m0 * DIN,
            g_wthi + (size_t)n0 * DIN, g_wtlo + (size_t)n0 * DIN };
        const uint32_t base = sb + buf * BUF_B;
        uint32_t so0 = (uint32_t)(r0row * LDS + r0k16 * 8) * 2;
        uint32_t so1 = (uint32_t)(r1row * LDS + r1k16 * 8) * 2;
#pragma unroll
        for (int t = 0; t < 4; t++) {
            cp_async16(base + t * TILE_B + so0,
                       srcs[t] + (size_t)r0row * DIN + k0 + r0k16 * 8);
            cp_async16(base + t * TILE_B + so1,
                       srcs[t] + (size_t)r1row * DIN + k0 + r1k16 * 8);
        }
        cp_commit();
    };

    issue_stage(0, 0);

#pragma unroll 1
    for (int kc = 0; kc < NKC; kc++) {
        cp_wait0();
        __syncthreads();
        if (kc + 1 < NKC) issue_stage(kc + 1, (kc + 1) & 1);

        const uint32_t bufb = sb + (kc & 1) * BUF_B;

#pragma unroll
        for (int term = 0; term < 3; term++) {
            const uint32_t ba = bufb + ((term == 2) ? TILE_B : 0);            /* A: hi,hi,lo */
            const uint32_t bb = bufb + 2 * TILE_B + ((term == 1) ? TILE_B : 0); /* B: hi,lo,hi */
#pragma unroll
            for (int ks = 0; ks < 2; ks++) {
                const uint32_t kbase = ks * 16;
                uint32_t afr[4][4];
#pragma unroll
                for (int i = 0; i < 4; i++) {
                    uint32_t row = wm * 64 + i * 16 + aRow;
                    ldm_x4(afr[i][0], afr[i][1], afr[i][2], afr[i][3],
                           ba + (row * LDS + kbase + aKof) * 2);
                }
                uint32_t bfr[2][4];
#pragma unroll
                for (int q = 0; q < 2; q++) {
                    uint32_t row = wn * 32 + q * 16 + bRow;
                    ldm_x4(bfr[q][0], bfr[q][1], bfr[q][2], bfr[q][3],
                           bb + (row * LDS + kbase + bKof) * 2);
                }
#pragma unroll
                for (int i = 0; i < 4; i++)
#pragma unroll
                    for (int j = 0; j < 4; j++)
                        mma16816(acc[i][j], afr[i], &bfr[j >> 1][(j & 1) * 2]);
            }
        }
        __syncthreads();
    }

    /* Epilogue: bias + activation, time-major gate write */
    const int gate = blockIdx.x >> 2;              /* 4 n-blocks per gate */
    const float* bias = (gate == 0) ? bi : (gate == 1) ? bfp : (gate == 2) ? bo : bz;
    float* outg = (gate == 0) ? g_gi : (gate == 1) ? g_gf : (gate == 2) ? g_go : g_gz;
    const int hblk = (blockIdx.x & 3) * 128;       /* h offset within gate */

#pragma unroll
    for (int i = 0; i < 4; i++) {
#pragma unroll
        for (int hh = 0; hh < 2; hh++) {
            int m = m0 + wm * 64 + i * 16 + (lane >> 2) + hh * 8;
            int b = m >> 12;
            int s = m & 4095;
            float* op = outg + (size_t)s * NCH + (size_t)b * DH;
#pragma unroll
            for (int j = 0; j < 4; j++) {
                int hcol = hblk + wn * 32 + j * 8 + (lane & 3) * 2;
                float v0 = acc[i][j][hh * 2 + 0] + bias[hcol + 0];
                float v1 = acc[i][j][hh * 2 + 1] + bias[hcol + 1];
                float r0, r1;
                if (gate <= 1) {
                    r0 = __expf(fminf(fmaxf(v0, -20.f), 0.f));
                    r1 = __expf(fminf(fmaxf(v1, -20.f), 0.f));
                } else if (gate == 2) {
                    r0 = 1.f / (1.f + __expf(-v0));
                    r1 = 1.f / (1.f + __expf(-v1));
                } else {
                    r0 = tanhf(v0);
                    r1 = tanhf(v1);
                }
                *(float2*)(op + hcol) = make_float2(r0, r1);
            }
        }
    }
}

/* ------------------------------------------------------------------ */
/* Scan (unchanged)                                                    */
/* ------------------------------------------------------------------ */
__global__ __launch_bounds__(128) void scan_passA()
{
    const int ch  = blockIdx.x * 128 + threadIdx.x;
    const int seg = blockIdx.y;
    const size_t off = (size_t)seg * TSEG * NCH + ch;
    const float* pf = g_gf + off;
    const float* pi = g_gi + off;
    const float* pz = g_gz + off;

    float A = 1.f, Bc = 0.f, Bn = 0.f;
#pragma unroll 1
    for (int t = 0; t < TSEG; t += 8) {
        float fv[8], iv[8], zv[8];
#pragma unroll
        for (int u = 0; u < 8; u++) {
            size_t idx = (size_t)(t + u) * NCH;
            fv[u] = pf[idx]; iv[u] = pi[idx]; zv[u] = pz[idx];
        }
#pragma unroll
        for (int u = 0; u < 8; u++) {
            Bc = fmaf(fv[u], Bc, iv[u] * zv[u]);
            Bn = fmaf(fv[u], Bn, iv[u]);
            A  = A * fv[u];
        }
    }
    g_A [(size_t)seg * NCH + ch] = A;
    g_Bc[(size_t)seg * NCH + ch] = Bc;
    g_Bn[(size_t)seg * NCH + ch] = Bn;
}

__global__ __launch_bounds__(128) void scan_passB()
{
    const int ch = blockIdx.x * 128 + threadIdx.x;
    float c = 0.f, n = 1.f;
#pragma unroll 1
    for (int sg = 0; sg < NSEG; sg++) {
        size_t idx = (size_t)sg * NCH + ch;
        g_Cs[idx] = c;
        g_Ns[idx] = n;
        float A  = g_A[idx];
        float Bc = g_Bc[idx];
        float Bn = g_Bn[idx];
        c = fmaf(A, c, Bc);
        n = fmaf(A, n, Bn);
    }
}

__global__ __launch_bounds__(128) void scan_passC(float* __restrict__ out)
{
    const int ch  = blockIdx.x * 128 + threadIdx.x;
    const int seg = blockIdx.y;
    const int b = ch >> 9;
    const int h = ch & 511;

    const size_t off = (size_t)seg * TSEG * NCH + ch;
    const float* pf = g_gf + off;
    const float* pi = g_gi + off;
    const float* po = g_go + off;
    const float* pz = g_gz + off;
    float* op = out + ((size_t)b * S_LEN + (size_t)seg * TSEG) * DH + h;

    size_t sidx = (size_t)seg * NCH + ch;
    float c = g_Cs[sidx];
    float n = g_Ns[sidx];

#pragma unroll 1
    for (int t = 0; t < TSEG; t += 8) {
        float fv[8], iv[8], ov[8], zv[8];
#pragma unroll
        for (int u = 0; u < 8; u++) {
            size_t idx = (size_t)(t + u) * NCH;
            fv[u] = pf[idx]; iv[u] = pi[idx]; ov[u] = po[idx]; zv[u] = pz[idx];
        }
#pragma unroll
        for (int u = 0; u < 8; u++) {
            c = fmaf(fv[u], c, iv[u] * zv[u]);
            n = fmaf(fv[u], n, iv[u]);
            op[(size_t)(t + u) * DH] = ov[u] * c / (n + 1e-6f);
        }
    }
}

/* ------------------------------------------------------------------ */
extern "C" void kernel_launch(void* const* d_in, const int* in_sizes, int n_in,
                              void* d_out, int out_size)
{
    const float* x  = (const float*)d_in[0];
    const float* Wi = (const float*)d_in[1];
    const float* bi = (const float*)d_in[2];
    const float* Wf = (const float*)d_in[3];
    const float* bf = (const float*)d_in[4];
    const float* Wo = (const float*)d_in[5];
    const float* bo = (const float*)d_in[6];
    const float* Wz = (const float*)d_in[7];
    const float* bz = (const float*)d_in[8];
    float* out = (float*)d_out;

    cudaFuncSetAttribute(gemm_hmma, cudaFuncAttributeMaxDynamicSharedMemorySize, GEMM_SMEM);

    convert_x<<<(MROWS * DIN / 4) / 256, 256>>>(x);
    convert_w<<<dim3(DIN / 32, DH / 32, 4), dim3(32, 8)>>>(Wi, Wf, Wo, Wz);

    gemm_hmma<<<dim3(NTOT / 128, MROWS / 128), 256, GEMM_SMEM>>>(bi, bf, bo, bz);

    dim3 gA(NCH / 128, NSEG);
    scan_passA<<<gA, 128>>>();
    scan_passB<<<NCH / 128, 128>>>();
    scan_passC<<<gA, 128>>>(out);
}

// round 7
// speedup vs baseline: 1.0826x; 1.0826x over previous
#include <cuda_runtime.h>
#include <cuda_bf16.h>
#include <cstdint>
#include <math.h>

#define S_LEN 4096
#define NB 8
#define DIN 256
#define DH 512
#define NCH (NB * DH)          /* 4096 channels */
#define MROWS (NB * S_LEN)     /* 32768 gemm rows */
#define NTOT (4 * DH)          /* 2048 concat N */

#define TSEG 64
#define NSEG (S_LEN / TSEG)

/* Gate scratch, time-major [S][B*H]. 64 MB each. */
__device__ float g_gi[S_LEN * NCH];
__device__ float g_gf[S_LEN * NCH];
__device__ float g_go[S_LEN * NCH];
__device__ float g_gz[S_LEN * NCH];

/* Segment aggregates / starts */
__device__ float g_A [NSEG * NCH];
__device__ float g_Bc[NSEG * NCH];
__device__ float g_Bn[NSEG * NCH];
__device__ float g_Cs[NSEG * NCH];
__device__ float g_Ns[NSEG * NCH];

/* bf16 split operands */
__device__ __nv_bfloat16 g_xhi[(size_t)MROWS * DIN];
__device__ __nv_bfloat16 g_xlo[(size_t)MROWS * DIN];
__device__ __nv_bfloat16 g_wthi[(size_t)NTOT * DIN];   /* transposed: [n_global][k] */
__device__ __nv_bfloat16 g_wtlo[(size_t)NTOT * DIN];

/* ------------------------------------------------------------------ */
__device__ __forceinline__ uint32_t smem_u32(const void* p) {
    uint32_t a;
    asm("{ .reg .u64 t; cvta.to.shared.u64 t, %1; cvt.u32.u64 %0, t; }" : "=r"(a) : "l"(p));
    return a;
}
__device__ __forceinline__ void cp_async16(uint32_t saddr, const void* g) {
    asm volatile("cp.async.cg.shared.global [%0], [%1], 16;" :: "r"(saddr), "l"(g));
}
__device__ __forceinline__ void cp_commit() {
    asm volatile("cp.async.commit_group;");
}
__device__ __forceinline__ void cp_wait1() {
    asm volatile("cp.async.wait_group 1;");
}
__device__ __forceinline__ void ldm_x4(uint32_t& r0, uint32_t& r1, uint32_t& r2, uint32_t& r3,
                                       uint32_t addr) {
    asm volatile("ldmatrix.sync.aligned.m8n8.x4.shared.b16 {%0,%1,%2,%3}, [%4];"
                 : "=r"(r0), "=r"(r1), "=r"(r2), "=r"(r3) : "r"(addr));
}
__device__ __forceinline__ void mma16816(float* c, const uint32_t* a, const uint32_t* b) {
    asm volatile(
        "mma.sync.aligned.m16n8k16.row.col.f32.bf16.bf16.f32 "
        "{%0,%1,%2,%3}, {%4,%5,%6,%7}, {%8,%9}, {%0,%1,%2,%3};"
        : "+f"(c[0]), "+f"(c[1]), "+f"(c[2]), "+f"(c[3])
        : "r"(a[0]), "r"(a[1]), "r"(a[2]), "r"(a[3]), "r"(b[0]), "r"(b[1]));
}

/* ------------------------------------------------------------------ */
/* Conversion kernels                                                  */
/* ------------------------------------------------------------------ */
__global__ __launch_bounds__(256) void convert_x(const float* __restrict__ x)
{
    size_t i = ((size_t)blockIdx.x * 256 + threadIdx.x) * 4;
    float4 v = *(const float4*)(x + i);
    float vv[4] = {v.x, v.y, v.z, v.w};
#pragma unroll
    for (int j = 0; j < 4; j++) {
        __nv_bfloat16 h = __float2bfloat16_rn(vv[j]);
        g_xhi[i + j] = h;
        g_xlo[i + j] = __float2bfloat16_rn(vv[j] - __bfloat162float(h));
    }
}

__global__ void convert_w(const float* __restrict__ Wi, const float* __restrict__ Wf,
                          const float* __restrict__ Wo, const float* __restrict__ Wz)
{
    const float* W = (blockIdx.z == 0) ? Wi : (blockIdx.z == 1) ? Wf
                   : (blockIdx.z == 2) ? Wo : Wz;
    __shared__ float t[32][33];
    int k0 = blockIdx.x * 32, n0 = blockIdx.y * 32;
    int tx = threadIdx.x, ty = threadIdx.y;    /* (32,8) */
#pragma unroll
    for (int j = 0; j < 4; j++)
        t[ty * 4 + j][tx] = W[(size_t)(k0 + ty * 4 + j) * DH + n0 + tx];
    __syncthreads();
#pragma unroll
    for (int j = 0; j < 4; j++) {
        float v = t[tx][ty * 4 + j];           /* k = k0+tx, n = n0+ty*4+j */
        size_t o = (size_t)(blockIdx.z * DH + n0 + ty * 4 + j) * DIN + k0 + tx;
        __nv_bfloat16 h = __float2bfloat16_rn(v);
        g_wthi[o] = h;
        g_wtlo[o] = __float2bfloat16_rn(v - __bfloat162float(h));
    }
}

/* ------------------------------------------------------------------ */
/* HMMA GEMM: [32768 x 256] x [256 x 2048], 3-term bf16 split          */
/* BM=128 BN=128 BK=32, 8 warps, warp tile 64x32.                      */
/* 3-stage cp.async pipeline, one __syncthreads per stage.             */
/* ------------------------------------------------------------------ */
#define LDS 40                         /* smem row stride in halves */
#define TILE_B (128 * LDS * 2)         /* 10240 B per operand tile */
#define STAGE_B (2 * TILE_B)           /* A + B = 20480 B per stage */
#define NSTAGE 3
#define GEMM_SMEM (NSTAGE * STAGE_B)   /* 61440 B */
#define NVK 24                         /* 3 terms x 8 k-chunks */

__global__ __launch_bounds__(256) void gemm_hmma(
    const float* __restrict__ bi, const float* __restrict__ bfp,
    const float* __restrict__ bo, const float* __restrict__ bz)
{
    extern __shared__ __align__(16) char smem[];

    const int tid  = threadIdx.x;
    const int lane = tid & 31;
    const int w    = tid >> 5;
    const int wm   = w & 1;          /* warp m index (0..1)  -> 64 rows  */
    const int wn   = w >> 1;         /* warp n index (0..3)  -> 32 cols  */

    const int m0 = blockIdx.y * 128;
    const int n0 = blockIdx.x * 128; /* global concat-n */

    const __nv_bfloat16* Asrc[3] = {g_xhi,  g_xhi,  g_xlo };
    const __nv_bfloat16* Bsrc[3] = {g_wthi, g_wtlo, g_wthi};

    const uint32_t sb = smem_u32(smem);

    float acc[4][4][4];
#pragma unroll
    for (int i = 0; i < 4; i++)
#pragma unroll
        for (int j = 0; j < 4; j++)
#pragma unroll
            for (int e = 0; e < 4; e++) acc[i][j][e] = 0.f;

    /* ldmatrix lane address components */
    const uint32_t aRow = (lane & 15);
    const uint32_t aKof = (lane >> 4) * 8;
    const uint32_t bRow = (lane & 7) + ((lane >> 4) << 3);
    const uint32_t bKof = ((lane >> 3) & 1) * 8;

    /* per-thread copy mapping: chunk c in [0,512): row=c>>2, k16=c&3 */
    const int r0row = tid >> 2;
    const int k16   = tid & 3;
    const int r1row = r0row + 64;

    auto issue_stage = [&](int vk) {
        const int term = vk >> 3;
        const int k0   = (vk & 7) * 32;
        const __nv_bfloat16* As = Asrc[term];
        const __nv_bfloat16* Bs = Bsrc[term];
        const uint32_t da = sb + (vk % NSTAGE) * STAGE_B;
        const uint32_t db = da + TILE_B;
        const uint32_t so0 = (uint32_t)(r0row * LDS + k16 * 8) * 2;
        const uint32_t so1 = (uint32_t)(r1row * LDS + k16 * 8) * 2;
        cp_async16(da + so0, As + (size_t)(m0 + r0row) * DIN + k0 + k16 * 8);
        cp_async16(da + so1, As + (size_t)(m0 + r1row) * DIN + k0 + k16 * 8);
        cp_async16(db + so0, Bs + (size_t)(n0 + r0row) * DIN + k0 + k16 * 8);
        cp_async16(db + so1, Bs + (size_t)(n0 + r1row) * DIN + k0 + k16 * 8);
        cp_commit();
    };

    issue_stage(0);
    issue_stage(1);

#pragma unroll 1
    for (int vk = 0; vk < NVK; vk++) {
        cp_wait1();                 /* stage vk landed (≤1 group outstanding) */
        __syncthreads();            /* all threads' data visible; WAR fence   */
        if (vk + 2 < NVK) issue_stage(vk + 2);

        const uint32_t ba = sb + (vk % NSTAGE) * STAGE_B;
        const uint32_t bb = ba + TILE_B;

#pragma unroll
        for (int ks = 0; ks < 2; ks++) {
            const uint32_t kbase = ks * 16;
            uint32_t afr[4][4];
#pragma unroll
            for (int i = 0; i < 4; i++) {
                uint32_t row = wm * 64 + i * 16 + aRow;
                ldm_x4(afr[i][0], afr[i][1], afr[i][2], afr[i][3],
                       ba + (row * LDS + kbase + aKof) * 2);
            }
            uint32_t bfr[2][4];
#pragma unroll
            for (int q = 0; q < 2; q++) {
                uint32_t row = wn * 32 + q * 16 + bRow;
                ldm_x4(bfr[q][0], bfr[q][1], bfr[q][2], bfr[q][3],
                       bb + (row * LDS + kbase + bKof) * 2);
            }
#pragma unroll
            for (int i = 0; i < 4; i++)
#pragma unroll
                for (int j = 0; j < 4; j++)
                    mma16816(acc[i][j], afr[i], &bfr[j >> 1][(j & 1) * 2]);
        }
    }

    /* Epilogue: bias + activation, time-major gate write */
    const int gate = blockIdx.x >> 2;              /* 4 n-blocks per gate */
    const float* bias = (gate == 0) ? bi : (gate == 1) ? bfp : (gate == 2) ? bo : bz;
    float* outg = (gate == 0) ? g_gi : (gate == 1) ? g_gf : (gate == 2) ? g_go : g_gz;
    const int hblk = (blockIdx.x & 3) * 128;       /* h offset within gate */

#pragma unroll
    for (int i = 0; i < 4; i++) {
#pragma unroll
        for (int hh = 0; hh < 2; hh++) {
            int m = m0 + wm * 64 + i * 16 + (lane >> 2) + hh * 8;
            int b = m >> 12;
            int s = m & 4095;
            float* op = outg + (size_t)s * NCH + (size_t)b * DH;
#pragma unroll
            for (int j = 0; j < 4; j++) {
                int hcol = hblk + wn * 32 + j * 8 + (lane & 3) * 2;
                float v0 = acc[i][j][hh * 2 + 0] + bias[hcol + 0];
                float v1 = acc[i][j][hh * 2 + 1] + bias[hcol + 1];
                float r0, r1;
                if (gate <= 1) {
                    r0 = __expf(fminf(fmaxf(v0, -20.f), 0.f));
                    r1 = __expf(fminf(fmaxf(v1, -20.f), 0.f));
                } else if (gate == 2) {
                    r0 = 1.f / (1.f + __expf(-v0));
                    r1 = 1.f / (1.f + __expf(-v1));
                } else {
                    r0 = tanhf(v0);
                    r1 = tanhf(v1);
                }
                *(float2*)(op + hcol) = make_float2(r0, r1);
            }
        }
    }
}

/* ------------------------------------------------------------------ */
/* Scan (unchanged)                                                    */
/* ------------------------------------------------------------------ */
__global__ __launch_bounds__(128) void scan_passA()
{
    const int ch  = blockIdx.x * 128 + threadIdx.x;
    const int seg = blockIdx.y;
    const size_t off = (size_t)seg * TSEG * NCH + ch;
    const float* pf = g_gf + off;
    const float* pi = g_gi + off;
    const float* pz = g_gz + off;

    float A = 1.f, Bc = 0.f, Bn = 0.f;
#pragma unroll 1
    for (int t = 0; t < TSEG; t += 8) {
        float fv[8], iv[8], zv[8];
#pragma unroll
        for (int u = 0; u < 8; u++) {
            size_t idx = (size_t)(t + u) * NCH;
            fv[u] = pf[idx]; iv[u] = pi[idx]; zv[u] = pz[idx];
        }
#pragma unroll
        for (int u = 0; u < 8; u++) {
            Bc = fmaf(fv[u], Bc, iv[u] * zv[u]);
            Bn = fmaf(fv[u], Bn, iv[u]);
            A  = A * fv[u];
        }
    }
    g_A [(size_t)seg * NCH + ch] = A;
    g_Bc[(size_t)seg * NCH + ch] = Bc;
    g_Bn[(size_t)seg * NCH + ch] = Bn;
}

__global__ __launch_bounds__(128) void scan_passB()
{
    const int ch = blockIdx.x * 128 + threadIdx.x;
    float c = 0.f, n = 1.f;
#pragma unroll 1
    for (int sg = 0; sg < NSEG; sg++) {
        size_t idx = (size_t)sg * NCH + ch;
        g_Cs[idx] = c;
        g_Ns[idx] = n;
        float A  = g_A[idx];
        float Bc = g_Bc[idx];
        float Bn = g_Bn[idx];
        c = fmaf(A, c, Bc);
        n = fmaf(A, n, Bn);
    }
}

__global__ __launch_bounds__(128) void scan_passC(float* __restrict__ out)
{
    const int ch  = blockIdx.x * 128 + threadIdx.x;
    const int seg = blockIdx.y;
    const int b = ch >> 9;
    const int h = ch & 511;

    const size_t off = (size_t)seg * TSEG * NCH + ch;
    const float* pf = g_gf + off;
    const float* pi = g_gi + off;
    const float* po = g_go + off;
    const float* pz = g_gz + off;
    float* op = out + ((size_t)b * S_LEN + (size_t)seg * TSEG) * DH + h;

    size_t sidx = (size_t)seg * NCH + ch;
    float c = g_Cs[sidx];
    float n = g_Ns[sidx];

#pragma unroll 1
    for (int t = 0; t < TSEG; t += 8) {
        float fv[8], iv[8], ov[8], zv[8];
#pragma unroll
        for (int u = 0; u < 8; u++) {
            size_t idx = (size_t)(t + u) * NCH;
            fv[u] = pf[idx]; iv[u] = pi[idx]; ov[u] = po[idx]; zv[u] = pz[idx];
        }
#pragma unroll
        for (int u = 0; u < 8; u++) {
            c = fmaf(fv[u], c, iv[u] * zv[u]);
            n = fmaf(fv[u], n, iv[u]);
            op[(size_t)(t + u) * DH] = ov[u] * c / (n + 1e-6f);
        }
    }
}

/* ------------------------------------------------------------------ */
extern "C" void kernel_launch(void* const* d_in, const int* in_sizes, int n_in,
                              void* d_out, int out_size)
{
    const float* x  = (const float*)d_in[0];
    const float* Wi = (const float*)d_in[1];
    const float* bi = (const float*)d_in[2];
    const float* Wf = (const float*)d_in[3];
    const float* bf = (const float*)d_in[4];
    const float* Wo = (const float*)d_in[5];
    const float* bo = (const float*)d_in[6];
    const float* Wz = (const float*)d_in[7];
    const float* bz = (const float*)d_in[8];
    float* out = (float*)d_out;

    cudaFuncSetAttribute(gemm_hmma, cudaFuncAttributeMaxDynamicSharedMemorySize, GEMM_SMEM);

    convert_x<<<(MROWS * DIN / 4) / 256, 256>>>(x);
    convert_w<<<dim3(DIN / 32, DH / 32, 4), dim3(32, 8)>>>(Wi, Wf, Wo, Wz);

    gemm_hmma<<<dim3(NTOT / 128, MROWS / 128), 256, GEMM_SMEM>>>(bi, bf, bo, bz);

    dim3 gA(NCH / 128, NSEG);
    scan_passA<<<gA, 128>>>();
    scan_passB<<<NCH / 128, 128>>>();
    scan_passC<<<gA, 128>>>(out);
}

// round 8
// speedup vs baseline: 1.2518x; 1.1562x over previous
#include <cuda_runtime.h>
#include <cuda_bf16.h>
#include <cstdint>
#include <math.h>

#define S_LEN 4096
#define NB 8
#define DIN 256
#define DH 512
#define NCH (NB * DH)          /* 4096 channels */
#define MROWS (NB * S_LEN)     /* 32768 gemm rows */
#define NTOT (4 * DH)          /* 2048 concat N */

#define TSEG 64
#define NSEG (S_LEN / TSEG)

/* Gate scratch, time-major [S][B*H]. 64 MB each. */
__device__ float g_gi[S_LEN * NCH];
__device__ float g_gf[S_LEN * NCH];
__device__ float g_go[S_LEN * NCH];
__device__ float g_gz[S_LEN * NCH];

/* Segment aggregates / starts */
__device__ float g_A [NSEG * NCH];
__device__ float g_Bc[NSEG * NCH];
__device__ float g_Bn[NSEG * NCH];
__device__ float g_Cs[NSEG * NCH];
__device__ float g_Ns[NSEG * NCH];

/* bf16 split operands */
__device__ __nv_bfloat16 g_xhi[(size_t)MROWS * DIN];
__device__ __nv_bfloat16 g_xlo[(size_t)MROWS * DIN];
__device__ __nv_bfloat16 g_wthi[(size_t)NTOT * DIN];   /* transposed: [n_global][k] */
__device__ __nv_bfloat16 g_wtlo[(size_t)NTOT * DIN];

/* ------------------------------------------------------------------ */
__device__ __forceinline__ uint32_t smem_u32(const void* p) {
    uint32_t a;
    asm("{ .reg .u64 t; cvta.to.shared.u64 t, %1; cvt.u32.u64 %0, t; }" : "=r"(a) : "l"(p));
    return a;
}
__device__ __forceinline__ void cp_async16(uint32_t saddr, const void* g) {
    asm volatile("cp.async.cg.shared.global [%0], [%1], 16;" :: "r"(saddr), "l"(g));
}
__device__ __forceinline__ void cp_commit() {
    asm volatile("cp.async.commit_group;");
}
__device__ __forceinline__ void cp_wait1() {
    asm volatile("cp.async.wait_group 1;");
}
__device__ __forceinline__ void ldm_x4(uint32_t& r0, uint32_t& r1, uint32_t& r2, uint32_t& r3,
                                       uint32_t addr) {
    asm volatile("ldmatrix.sync.aligned.m8n8.x4.shared.b16 {%0,%1,%2,%3}, [%4];"
                 : "=r"(r0), "=r"(r1), "=r"(r2), "=r"(r3) : "r"(addr));
}
__device__ __forceinline__ void mma16816(float* c, const uint32_t* a, const uint32_t* b) {
    asm volatile(
        "mma.sync.aligned.m16n8k16.row.col.f32.bf16.bf16.f32 "
        "{%0,%1,%2,%3}, {%4,%5,%6,%7}, {%8,%9}, {%0,%1,%2,%3};"
        : "+f"(c[0]), "+f"(c[1]), "+f"(c[2]), "+f"(c[3])
        : "r"(a[0]), "r"(a[1]), "r"(a[2]), "r"(a[3]), "r"(b[0]), "r"(b[1]));
}

/* ------------------------------------------------------------------ */
/* Conversion kernels                                                  */
/* ------------------------------------------------------------------ */
__global__ __launch_bounds__(256) void convert_x(const float* __restrict__ x)
{
    size_t i = ((size_t)blockIdx.x * 256 + threadIdx.x) * 4;
    float4 v = *(const float4*)(x + i);
    float vv[4] = {v.x, v.y, v.z, v.w};
#pragma unroll
    for (int j = 0; j < 4; j++) {
        __nv_bfloat16 h = __float2bfloat16_rn(vv[j]);
        g_xhi[i + j] = h;
        g_xlo[i + j] = __float2bfloat16_rn(vv[j] - __bfloat162float(h));
    }
}

__global__ void convert_w(const float* __restrict__ Wi, const float* __restrict__ Wf,
                          const float* __restrict__ Wo, const float* __restrict__ Wz)
{
    const float* W = (blockIdx.z == 0) ? Wi : (blockIdx.z == 1) ? Wf
                   : (blockIdx.z == 2) ? Wo : Wz;
    __shared__ float t[32][33];
    int k0 = blockIdx.x * 32, n0 = blockIdx.y * 32;
    int tx = threadIdx.x, ty = threadIdx.y;    /* (32,8) */
#pragma unroll
    for (int j = 0; j < 4; j++)
        t[ty * 4 + j][tx] = W[(size_t)(k0 + ty * 4 + j) * DH + n0 + tx];
    __syncthreads();
#pragma unroll
    for (int j = 0; j < 4; j++) {
        float v = t[tx][ty * 4 + j];           /* k = k0+tx, n = n0+ty*4+j */
        size_t o = (size_t)(blockIdx.z * DH + n0 + ty * 4 + j) * DIN + k0 + tx;
        __nv_bfloat16 h = __float2bfloat16_rn(v);
        g_wthi[o] = h;
        g_wtlo[o] = __float2bfloat16_rn(v - __bfloat162float(h));
    }
}

/* ------------------------------------------------------------------ */
/* HMMA GEMM, 3-term bf16 split, quad stages + register frag reuse.    */
/* BM=128 BN=128 BK=32, 8 warps (2x4), warp tile 64x32.                */
/* Stage = {A_hi, A_lo, B_hi, B_lo} for one 32-wide k-chunk.           */
/* ------------------------------------------------------------------ */
#define LDS 40                          /* smem row stride in halves */
#define TILE_B (128 * LDS * 2)          /* 10240 B per operand tile */
#define STAGE_B (4 * TILE_B)            /* 40960 B per quad stage */
#define GEMM_SMEM (2 * STAGE_B)         /* 81920 B */
#define NKC 8                           /* 8 k-chunks of 32 */

__global__ __launch_bounds__(256) void gemm_hmma(
    const float* __restrict__ bi, const float* __restrict__ bfp,
    const float* __restrict__ bo, const float* __restrict__ bz)
{
    extern __shared__ __align__(16) char smem[];

    const int tid  = threadIdx.x;
    const int lane = tid & 31;
    const int w    = tid >> 5;
    const int wm   = w & 1;          /* warp m index (0..1)  -> 64 rows  */
    const int wn   = w >> 1;         /* warp n index (0..3)  -> 32 cols  */

    const int m0 = blockIdx.y * 128;
    const int n0 = blockIdx.x * 128; /* global concat-n */

    const uint32_t sb = smem_u32(smem);

    float acc[4][4][4];
#pragma unroll
    for (int i = 0; i < 4; i++)
#pragma unroll
        for (int j = 0; j < 4; j++)
#pragma unroll
            for (int e = 0; e < 4; e++) acc[i][j][e] = 0.f;

    /* ldmatrix lane address components */
    const uint32_t aRow = (lane & 15);
    const uint32_t aKof = (lane >> 4) * 8;
    const uint32_t bRow = (lane & 7) + ((lane >> 4) << 3);
    const uint32_t bKof = ((lane >> 3) & 1) * 8;

    /* cp.async mapping: per tile, thread covers rows tid>>2 and +64, k16=tid&3 */
    const int r0row = tid >> 2;
    const int k16   = tid & 3;
    const int r1row = r0row + 64;

    auto issue_stage = [&](int kc, int buf) {
        const int k0 = kc * 32;
        const __nv_bfloat16* srcs[4] = {
            g_xhi  + (size_t)m0 * DIN, g_xlo  + (size_t)m0 * DIN,
            g_wthi + (size_t)n0 * DIN, g_wtlo + (size_t)n0 * DIN };
        const uint32_t base = sb + buf * STAGE_B;
        const uint32_t so0 = (uint32_t)(r0row * LDS + k16 * 8) * 2;
        const uint32_t so1 = (uint32_t)(r1row * LDS + k16 * 8) * 2;
#pragma unroll
        for (int t = 0; t < 4; t++) {
            cp_async16(base + t * TILE_B + so0,
                       srcs[t] + (size_t)r0row * DIN + k0 + k16 * 8);
            cp_async16(base + t * TILE_B + so1,
                       srcs[t] + (size_t)r1row * DIN + k0 + k16 * 8);
        }
        cp_commit();
    };

    issue_stage(0, 0);
    issue_stage(1, 1);

#pragma unroll 1
    for (int kc = 0; kc < NKC; kc++) {
        cp_wait1();                 /* stage kc landed */
        __syncthreads();

        const uint32_t bufb = sb + (kc & 1) * STAGE_B;
        const uint32_t tAhi = bufb;
        const uint32_t tAlo = bufb + TILE_B;
        const uint32_t tBhi = bufb + 2 * TILE_B;
        const uint32_t tBlo = bufb + 3 * TILE_B;

#pragma unroll
        for (int ks = 0; ks < 2; ks++) {
            const uint32_t kbase = ks * 16;
            uint32_t afr[4][4];
            uint32_t bhi[2][4], blo[2][4];
#pragma unroll
            for (int i = 0; i < 4; i++) {
                uint32_t row = wm * 64 + i * 16 + aRow;
                ldm_x4(afr[i][0], afr[i][1], afr[i][2], afr[i][3],
                       tAhi + (row * LDS + kbase + aKof) * 2);
            }
#pragma unroll
            for (int q = 0; q < 2; q++) {
                uint32_t row = wn * 32 + q * 16 + bRow;
                ldm_x4(bhi[q][0], bhi[q][1], bhi[q][2], bhi[q][3],
                       tBhi + (row * LDS + kbase + bKof) * 2);
                ldm_x4(blo[q][0], blo[q][1], blo[q][2], blo[q][3],
                       tBlo + (row * LDS + kbase + bKof) * 2);
            }
            /* term 0: A_hi x B_hi ; term 1: A_hi x B_lo */
#pragma unroll
            for (int i = 0; i < 4; i++)
#pragma unroll
                for (int j = 0; j < 4; j++) {
                    mma16816(acc[i][j], afr[i], &bhi[j >> 1][(j & 1) * 2]);
                    mma16816(acc[i][j], afr[i], &blo[j >> 1][(j & 1) * 2]);
                }
            /* reload afr with A_lo, term 2: A_lo x B_hi */
#pragma unroll
            for (int i = 0; i < 4; i++) {
                uint32_t row = wm * 64 + i * 16 + aRow;
                ldm_x4(afr[i][0], afr[i][1], afr[i][2], afr[i][3],
                       tAlo + (row * LDS + kbase + aKof) * 2);
            }
#pragma unroll
            for (int i = 0; i < 4; i++)
#pragma unroll
                for (int j = 0; j < 4; j++)
                    mma16816(acc[i][j], afr[i], &bhi[j >> 1][(j & 1) * 2]);
        }

        __syncthreads();            /* compute done before buffer reuse */
        if (kc + 2 < NKC) issue_stage(kc + 2, kc & 1);
    }

    /* Epilogue: bias + activation, time-major gate write */
    const int gate = blockIdx.x >> 2;              /* 4 n-blocks per gate */
    const float* bias = (gate == 0) ? bi : (gate == 1) ? bfp : (gate == 2) ? bo : bz;
    float* outg = (gate == 0) ? g_gi : (gate == 1) ? g_gf : (gate == 2) ? g_go : g_gz;
    const int hblk = (blockIdx.x & 3) * 128;       /* h offset within gate */

#pragma unroll
    for (int i = 0; i < 4; i++) {
#pragma unroll
        for (int hh = 0; hh < 2; hh++) {
            int m = m0 + wm * 64 + i * 16 + (lane >> 2) + hh * 8;
            int b = m >> 12;
            int s = m & 4095;
            float* op = outg + (size_t)s * NCH + (size_t)b * DH;
#pragma unroll
            for (int j = 0; j < 4; j++) {
                int hcol = hblk + wn * 32 + j * 8 + (lane & 3) * 2;
                float v0 = acc[i][j][hh * 2 + 0] + bias[hcol + 0];
                float v1 = acc[i][j][hh * 2 + 1] + bias[hcol + 1];
                float r0, r1;
                if (gate <= 1) {
                    r0 = __expf(fminf(fmaxf(v0, -20.f), 0.f));
                    r1 = __expf(fminf(fmaxf(v1, -20.f), 0.f));
                } else if (gate == 2) {
                    r0 = 1.f / (1.f + __expf(-v0));
                    r1 = 1.f / (1.f + __expf(-v1));
                } else {
                    r0 = tanhf(v0);
                    r1 = tanhf(v1);
                }
                *(float2*)(op + hcol) = make_float2(r0, r1);
            }
        }
    }
}

/* ------------------------------------------------------------------ */
/* Scan (unchanged)                                                    */
/* ------------------------------------------------------------------ */
__global__ __launch_bounds__(128) void scan_passA()
{
    const int ch  = blockIdx.x * 128 + threadIdx.x;
    const int seg = blockIdx.y;
    const size_t off = (size_t)seg * TSEG * NCH + ch;
    const float* pf = g_gf + off;
    const float* pi = g_gi + off;
    const float* pz = g_gz + off;

    float A = 1.f, Bc = 0.f, Bn = 0.f;
#pragma unroll 1
    for (int t = 0; t < TSEG; t += 8) {
        float fv[8], iv[8], zv[8];
#pragma unroll
        for (int u = 0; u < 8; u++) {
            size_t idx = (size_t)(t + u) * NCH;
            fv[u] = pf[idx]; iv[u] = pi[idx]; zv[u] = pz[idx];
        }
#pragma unroll
        for (int u = 0; u < 8; u++) {
            Bc = fmaf(fv[u], Bc, iv[u] * zv[u]);
            Bn = fmaf(fv[u], Bn, iv[u]);
            A  = A * fv[u];
        }
    }
    g_A [(size_t)seg * NCH + ch] = A;
    g_Bc[(size_t)seg * NCH + ch] = Bc;
    g_Bn[(size_t)seg * NCH + ch] = Bn;
}

__global__ __launch_bounds__(128) void scan_passB()
{
    const int ch = blockIdx.x * 128 + threadIdx.x;
    float c = 0.f, n = 1.f;
#pragma unroll 1
    for (int sg = 0; sg < NSEG; sg++) {
        size_t idx = (size_t)sg * NCH + ch;
        g_Cs[idx] = c;
        g_Ns[idx] = n;
        float A  = g_A[idx];
        float Bc = g_Bc[idx];
        float Bn = g_Bn[idx];
        c = fmaf(A, c, Bc);
        n = fmaf(A, n, Bn);
    }
}

__global__ __launch_bounds__(128) void scan_passC(float* __restrict__ out)
{
    const int ch  = blockIdx.x * 128 + threadIdx.x;
    const int seg = blockIdx.y;
    const int b = ch >> 9;
    const int h = ch & 511;

    const size_t off = (size_t)seg * TSEG * NCH + ch;
    const float* pf = g_gf + off;
    const float* pi = g_gi + off;
    const float* po = g_go + off;
    const float* pz = g_gz + off;
    float* op = out + ((size_t)b * S_LEN + (size_t)seg * TSEG) * DH + h;

    size_t sidx = (size_t)seg * NCH + ch;
    float c = g_Cs[sidx];
    float n = g_Ns[sidx];

#pragma unroll 1
    for (int t = 0; t < TSEG; t += 8) {
        float fv[8], iv[8], ov[8], zv[8];
#pragma unroll
        for (int u = 0; u < 8; u++) {
            size_t idx = (size_t)(t + u) * NCH;
            fv[u] = pf[idx]; iv[u] = pi[idx]; ov[u] = po[idx]; zv[u] = pz[idx];
        }
#pragma unroll
        for (int u = 0; u < 8; u++) {
            c = fmaf(fv[u], c, iv[u] * zv[u]);
            n = fmaf(fv[u], n, iv[u]);
            op[(size_t)(t + u) * DH] = ov[u] * c / (n + 1e-6f);
        }
    }
}

/* ------------------------------------------------------------------ */
extern "C" void kernel_launch(void* const* d_in, const int* in_sizes, int n_in,
                              void* d_out, int out_size)
{
    const float* x  = (const float*)d_in[0];
    const float* Wi = (const float*)d_in[1];
    const float* bi = (const float*)d_in[2];
    const float* Wf = (const float*)d_in[3];
    const float* bf = (const float*)d_in[4];
    const float* Wo = (const float*)d_in[5];
    const float* bo = (const float*)d_in[6];
    const float* Wz = (const float*)d_in[7];
    const float* bz = (const float*)d_in[8];
    float* out = (float*)d_out;

    cudaFuncSetAttribute(gemm_hmma, cudaFuncAttributeMaxDynamicSharedMemorySize, GEMM_SMEM);

    convert_x<<<(MROWS * DIN / 4) / 256, 256>>>(x);
    convert_w<<<dim3(DIN / 32, DH / 32, 4), dim3(32, 8)>>>(Wi, Wf, Wo, Wz);

    gemm_hmma<<<dim3(NTOT / 128, MROWS / 128), 256, GEMM_SMEM>>>(bi, bf, bo, bz);

    dim3 gA(NCH / 128, NSEG);
    scan_passA<<<gA, 128>>>();
    scan_passB<<<NCH / 128, 128>>>();
    scan_passC<<<gA, 128>>>(out);
}

// round 10
// speedup vs baseline: 1.5133x; 1.2090x over previous
#include <cuda_runtime.h>
#include <cuda_fp16.h>
#include <cstdint>
#include <math.h>

#define S_LEN 4096
#define NB 8
#define DIN 256
#define DH 512
#define NCH (NB * DH)          /* 4096 channels */
#define MROWS (NB * S_LEN)     /* 32768 gemm rows */
#define NTOT (4 * DH)          /* 2048 concat N */

#define TSEG 64
#define NSEG (S_LEN / TSEG)

/* Gate scratch, time-major [S][B*H]. 64 MB each. */
__device__ float g_gi[S_LEN * NCH];
__device__ float g_gf[S_LEN * NCH];
__device__ float g_go[S_LEN * NCH];
__device__ float g_gz[S_LEN * NCH];

/* Segment aggregates / starts */
__device__ float g_A [NSEG * NCH];
__device__ float g_Bc[NSEG * NCH];
__device__ float g_Bn[NSEG * NCH];
__device__ float g_Cs[NSEG * NCH];
__device__ float g_Ns[NSEG * NCH];

/* fp16 operands: x split hi/lo, W single fp16 (transposed) */
__device__ __half g_xhi[(size_t)MROWS * DIN];
__device__ __half g_xlo[(size_t)MROWS * DIN];
__device__ __half g_wt [(size_t)NTOT * DIN];    /* transposed: [n_global][k] */

/* ------------------------------------------------------------------ */
__device__ __forceinline__ uint32_t smem_u32(const void* p) {
    uint32_t a;
    asm("{ .reg .u64 t; cvta.to.shared.u64 t, %1; cvt.u32.u64 %0, t; }" : "=r"(a) : "l"(p));
    return a;
}
__device__ __forceinline__ void cp_async16(uint32_t saddr, const void* g) {
    asm volatile("cp.async.cg.shared.global [%0], [%1], 16;" :: "r"(saddr), "l"(g));
}
__device__ __forceinline__ void cp_commit() {
    asm volatile("cp.async.commit_group;");
}
__device__ __forceinline__ void cp_wait1() {
    asm volatile("cp.async.wait_group 1;");
}
__device__ __forceinline__ void ldm_x4(uint32_t& r0, uint32_t& r1, uint32_t& r2, uint32_t& r3,
                                       uint32_t addr) {
    asm volatile("ldmatrix.sync.aligned.m8n8.x4.shared.b16 {%0,%1,%2,%3}, [%4];"
                 : "=r"(r0), "=r"(r1), "=r"(r2), "=r"(r3) : "r"(addr));
}
__device__ __forceinline__ void mma16816(float* c, const uint32_t* a, const uint32_t* b) {
    asm volatile(
        "mma.sync.aligned.m16n8k16.row.col.f32.f16.f16.f32 "
        "{%0,%1,%2,%3}, {%4,%5,%6,%7}, {%8,%9}, {%0,%1,%2,%3};"
        : "+f"(c[0]), "+f"(c[1]), "+f"(c[2]), "+f"(c[3])
        : "r"(a[0]), "r"(a[1]), "r"(a[2]), "r"(a[3]), "r"(b[0]), "r"(b[1]));
}

/* ------------------------------------------------------------------ */
/* Conversion kernels                                                  */
/* ------------------------------------------------------------------ */
__global__ __launch_bounds__(256) void convert_x(const float* __restrict__ x)
{
    size_t i = ((size_t)blockIdx.x * 256 + threadIdx.x) * 4;
    float4 v = *(const float4*)(x + i);
    float vv[4] = {v.x, v.y, v.z, v.w};
#pragma unroll
    for (int j = 0; j < 4; j++) {
        __half h = __float2half_rn(vv[j]);
        g_xhi[i + j] = h;
        g_xlo[i + j] = __float2half_rn(vv[j] - __half2float(h));
    }
}

__global__ void convert_w(const float* __restrict__ Wi, const float* __restrict__ Wf,
                          const float* __restrict__ Wo, const float* __restrict__ Wz)
{
    const float* W = (blockIdx.z == 0) ? Wi : (blockIdx.z == 1) ? Wf
                   : (blockIdx.z == 2) ? Wo : Wz;
    __shared__ float t[32][33];
    int k0 = blockIdx.x * 32, n0 = blockIdx.y * 32;
    int tx = threadIdx.x, ty = threadIdx.y;    /* (32,8) */
#pragma unroll
    for (int j = 0; j < 4; j++)
        t[ty * 4 + j][tx] = W[(size_t)(k0 + ty * 4 + j) * DH + n0 + tx];
    __syncthreads();
#pragma unroll
    for (int j = 0; j < 4; j++) {
        float v = t[tx][ty * 4 + j];           /* k = k0+tx, n = n0+ty*4+j */
        size_t o = (size_t)(blockIdx.z * DH + n0 + ty * 4 + j) * DIN + k0 + tx;
        g_wt[o] = __float2half_rn(v);
    }
}

/* ------------------------------------------------------------------ */
/* HMMA GEMM, 2-term fp16 split: v = x_hi*W + x_lo*W.                  */
/* BM=128 BN=128 BK=32, 8 warps (2x4), warp tile 64x32.                */
/* Stage = {A_hi, A_lo, B} for one 32-wide k-chunk; 2-buffer pipeline. */
/* ------------------------------------------------------------------ */
#define LDS 40                          /* smem row stride in halves */
#define TILE_B (128 * LDS * 2)          /* 10240 B per operand tile */
#define STAGE_B (3 * TILE_B)            /* 30720 B per stage */
#define GEMM_SMEM (2 * STAGE_B)         /* 61440 B */
#define NKC 8                           /* 8 k-chunks of 32 */

__global__ __launch_bounds__(256) void gemm_hmma(
    const float* __restrict__ bi, const float* __restrict__ bfp,
    const float* __restrict__ bo, const float* __restrict__ bz)
{
    extern __shared__ __align__(16) char smem[];

    const int tid  = threadIdx.x;
    const int lane = tid & 31;
    const int w    = tid >> 5;
    const int wm   = w & 1;          /* warp m index (0..1)  -> 64 rows  */
    const int wn   = w >> 1;         /* warp n index (0..3)  -> 32 cols  */

    const int m0 = blockIdx.y * 128;
    const int n0 = blockIdx.x * 128; /* global concat-n */

    const uint32_t sb = smem_u32(smem);

    float acc[4][4][4];
#pragma unroll
    for (int i = 0; i < 4; i++)
#pragma unroll
        for (int j = 0; j < 4; j++)
#pragma unroll
            for (int e = 0; e < 4; e++) acc[i][j][e] = 0.f;

    /* ldmatrix lane address components */
    const uint32_t aRow = (lane & 15);
    const uint32_t aKof = (lane >> 4) * 8;
    const uint32_t bRow = (lane & 7) + ((lane >> 4) << 3);
    const uint32_t bKof = ((lane >> 3) & 1) * 8;

    /* cp.async mapping: per tile, thread covers rows tid>>2 and +64, k16=tid&3 */
    const int r0row = tid >> 2;
    const int k16   = tid & 3;
    const int r1row = r0row + 64;

    auto issue_stage = [&](int kc, int buf) {
        const int k0 = kc * 32;
        const __half* srcs[3] = {
            g_xhi + (size_t)m0 * DIN, g_xlo + (size_t)m0 * DIN,
            g_wt  + (size_t)n0 * DIN };
        const uint32_t base = sb + buf * STAGE_B;
        const uint32_t so0 = (uint32_t)(r0row * LDS + k16 * 8) * 2;
        const uint32_t so1 = (uint32_t)(r1row * LDS + k16 * 8) * 2;
#pragma unroll
        for (int t = 0; t < 3; t++) {
            cp_async16(base + t * TILE_B + so0,
                       srcs[t] + (size_t)r0row * DIN + k0 + k16 * 8);
            cp_async16(base + t * TILE_B + so1,
                       srcs[t] + (size_t)r1row * DIN + k0 + k16 * 8);
        }
        cp_commit();
    };

    issue_stage(0, 0);
    issue_stage(1, 1);

#pragma unroll 1
    for (int kc = 0; kc < NKC; kc++) {
        cp_wait1();                 /* stage kc landed */
        __syncthreads();

        const uint32_t bufb = sb + (kc & 1) * STAGE_B;
        const uint32_t tAhi = bufb;
        const uint32_t tAlo = bufb + TILE_B;
        const uint32_t tB   = bufb + 2 * TILE_B;

#pragma unroll
        for (int ks = 0; ks < 2; ks++) {
            const uint32_t kbase = ks * 16;
            uint32_t afr[4][4];
            uint32_t bfr[2][4];
#pragma unroll
            for (int q = 0; q < 2; q++) {
                uint32_t row = wn * 32 + q * 16 + bRow;
                ldm_x4(bfr[q][0], bfr[q][1], bfr[q][2], bfr[q][3],
                       tB + (row * LDS + kbase + bKof) * 2);
            }
            /* term 0: A_hi x B */
#pragma unroll
            for (int i = 0; i < 4; i++) {
                uint32_t row = wm * 64 + i * 16 + aRow;
                ldm_x4(afr[i][0], afr[i][1], afr[i][2], afr[i][3],
                       tAhi + (row * LDS + kbase + aKof) * 2);
            }
#pragma unroll
            for (int i = 0; i < 4; i++)
#pragma unroll
                for (int j = 0; j < 4; j++)
                    mma16816(acc[i][j], afr[i], &bfr[j >> 1][(j & 1) * 2]);
            /* term 1: A_lo x B (reuse afr regs) */
#pragma unroll
            for (int i = 0; i < 4; i++) {
                uint32_t row = wm * 64 + i * 16 + aRow;
                ldm_x4(afr[i][0], afr[i][1], afr[i][2], afr[i][3],
                       tAlo + (row * LDS + kbase + aKof) * 2);
            }
#pragma unroll
            for (int i = 0; i < 4; i++)
#pragma unroll
                for (int j = 0; j < 4; j++)
                    mma16816(acc[i][j], afr[i], &bfr[j >> 1][(j & 1) * 2]);
        }

        __syncthreads();            /* compute done before buffer reuse */
        if (kc + 2 < NKC) issue_stage(kc + 2, kc & 1);
    }

    /* Epilogue: bias + activation, time-major gate write */
    const int gate = blockIdx.x >> 2;              /* 4 n-blocks per gate */
    const float* bias = (gate == 0) ? bi : (gate == 1) ? bfp : (gate == 2) ? bo : bz;
    float* outg = (gate == 0) ? g_gi : (gate == 1) ? g_gf : (gate == 2) ? g_go : g_gz;
    const int hblk = (blockIdx.x & 3) * 128;       /* h offset within gate */

#pragma unroll
    for (int i = 0; i < 4; i++) {
#pragma unroll
        for (int hh = 0; hh < 2; hh++) {
            int m = m0 + wm * 64 + i * 16 + (lane >> 2) + hh * 8;
            int b = m >> 12;
            int s = m & 4095;
            float* op = outg + (size_t)s * NCH + (size_t)b * DH;
#pragma unroll
            for (int j = 0; j < 4; j++) {
                int hcol = hblk + wn * 32 + j * 8 + (lane & 3) * 2;
                float v0 = acc[i][j][hh * 2 + 0] + bias[hcol + 0];
                float v1 = acc[i][j][hh * 2 + 1] + bias[hcol + 1];
                float r0, r1;
                if (gate <= 1) {
                    r0 = __expf(fminf(fmaxf(v0, -20.f), 0.f));
                    r1 = __expf(fminf(fmaxf(v1, -20.f), 0.f));
                } else if (gate == 2) {
                    r0 = 1.f / (1.f + __expf(-v0));
                    r1 = 1.f / (1.f + __expf(-v1));
                } else {
                    r0 = tanhf(v0);
                    r1 = tanhf(v1);
                }
                *(float2*)(op + hcol) = make_float2(r0, r1);
            }
        }
    }
}

/* ------------------------------------------------------------------ */
/* Scan (unchanged)                                                    */
/* ------------------------------------------------------------------ */
__global__ __launch_bounds__(128) void scan_passA()
{
    const int ch  = blockIdx.x * 128 + threadIdx.x;
    const int seg = blockIdx.y;
    const size_t off = (size_t)seg * TSEG * NCH + ch;
    const float* pf = g_gf + off;
    const float* pi = g_gi + off;
    const float* pz = g_gz + off;

    float A = 1.f, Bc = 0.f, Bn = 0.f;
#pragma unroll 1
    for (int t = 0; t < TSEG; t += 8) {
        float fv[8], iv[8], zv[8];
#pragma unroll
        for (int u = 0; u < 8; u++) {
            size_t idx = (size_t)(t + u) * NCH;
            fv[u] = pf[idx]; iv[u] = pi[idx]; zv[u] = pz[idx];
        }
#pragma unroll
        for (int u = 0; u < 8; u++) {
            Bc = fmaf(fv[u], Bc, iv[u] * zv[u]);
            Bn = fmaf(fv[u], Bn, iv[u]);
            A  = A * fv[u];
        }
    }
    g_A [(size_t)seg * NCH + ch] = A;
    g_Bc[(size_t)seg * NCH + ch] = Bc;
    g_Bn[(size_t)seg * NCH + ch] = Bn;
}

__global__ __launch_bounds__(128) void scan_passB()
{
    const int ch = blockIdx.x * 128 + threadIdx.x;
    float c = 0.f, n = 1.f;
#pragma unroll 1
    for (int sg = 0; sg < NSEG; sg++) {
        size_t idx = (size_t)sg * NCH + ch;
        g_Cs[idx] = c;
        g_Ns[idx] = n;
        float A  = g_A[idx];
        float Bc = g_Bc[idx];
        float Bn = g_Bn[idx];
        c = fmaf(A, c, Bc);
        n = fmaf(A, n, Bn);
    }
}

__global__ __launch_bounds__(128) void scan_passC(float* __restrict__ out)
{
    const int ch  = blockIdx.x * 128 + threadIdx.x;
    const int seg = blockIdx.y;
    const int b = ch >> 9;
    const int h = ch & 511;

    const size_t off = (size_t)seg * TSEG * NCH + ch;
    const float* pf = g_gf + off;
    const float* pi = g_gi + off;
    const float* po = g_go + off;
    const float* pz = g_gz + off;
    float* op = out + ((size_t)b * S_LEN + (size_t)seg * TSEG) * DH + h;

    size_t sidx = (size_t)seg * NCH + ch;
    float c = g_Cs[sidx];
    float n = g_Ns[sidx];

#pragma unroll 1
    for (int t = 0; t < TSEG; t += 8) {
        float fv[8], iv[8], ov[8], zv[8];
#pragma unroll
        for (int u = 0; u < 8; u++) {
            size_t idx = (size_t)(t + u) * NCH;
            fv[u] = pf[idx]; iv[u] = pi[idx]; ov[u] = po[idx]; zv[u] = pz[idx];
        }
#pragma unroll
        for (int u = 0; u < 8; u++) {
            c = fmaf(fv[u], c, iv[u] * zv[u]);
            n = fmaf(fv[u], n, iv[u]);
            op[(size_t)(t + u) * DH] = ov[u] * c / (n + 1e-6f);
        }
    }
}

/* ------------------------------------------------------------------ */
extern "C" void kernel_launch(void* const* d_in, const int* in_sizes, int n_in,
                              void* d_out, int out_size)
{
    const float* x  = (const float*)d_in[0];
    const float* Wi = (const float*)d_in[1];
    const float* bi = (const float*)d_in[2];
    const float* Wf = (const float*)d_in[3];
    const float* bf = (const float*)d_in[4];
    const float* Wo = (const float*)d_in[5];
    const float* bo = (const float*)d_in[6];
    const float* Wz = (const float*)d_in[7];
    const float* bz = (const float*)d_in[8];
    float* out = (float*)d_out;

    cudaFuncSetAttribute(gemm_hmma, cudaFuncAttributeMaxDynamicSharedMemorySize, GEMM_SMEM);

    convert_x<<<(MROWS * DIN / 4) / 256, 256>>>(x);
    convert_w<<<dim3(DIN / 32, DH / 32, 4), dim3(32, 8)>>>(Wi, Wf, Wo, Wz);

    gemm_hmma<<<dim3(NTOT / 128, MROWS / 128), 256, GEMM_SMEM>>>(bi, bf, bo, bz);

    dim3 gA(NCH / 128, NSEG);
    scan_passA<<<gA, 128>>>();
    scan_passB<<<NCH / 128, 128>>>();
    scan_passC<<<gA, 128>>>(out);
}

// round 15
// speedup vs baseline: 1.8930x; 1.2509x over previous
#include <cuda_runtime.h>
#include <cuda_fp16.h>
#include <cstdint>
#include <math.h>

#define S_LEN 4096
#define NB 8
#define DIN 256
#define DH 512
#define NCH (NB * DH)          /* 4096 channels */
#define MROWS (NB * S_LEN)     /* 32768 gemm rows */
#define NTOT (4 * DH)          /* 2048 concat N */

#define TSEG 64
#define NSEG (S_LEN / TSEG)

/* Gate scratch, time-major [S][B*H]. 64 MB each. */
__device__ float g_gi[S_LEN * NCH];
__device__ float g_gf[S_LEN * NCH];
__device__ float g_go[S_LEN * NCH];
__device__ float g_gz[S_LEN * NCH];

/* Segment aggregates / starts */
__device__ float g_A [NSEG * NCH];
__device__ float g_Bc[NSEG * NCH];
__device__ float g_Bn[NSEG * NCH];
__device__ float g_Cs[NSEG * NCH];
__device__ float g_Ns[NSEG * NCH];

/* fp16 operands */
__device__ __half g_xh[(size_t)MROWS * DIN];
__device__ __half g_wt[(size_t)NTOT * DIN];    /* transposed: [n_global][k] */

/* ------------------------------------------------------------------ */
__device__ __forceinline__ uint32_t smem_u32(const void* p) {
    uint32_t a;
    asm("{ .reg .u64 t; cvta.to.shared.u64 t, %1; cvt.u32.u64 %0, t; }" : "=r"(a) : "l"(p));
    return a;
}
__device__ __forceinline__ void cp_async16(uint32_t saddr, const void* g) {
    asm volatile("cp.async.cg.shared.global [%0], [%1], 16;" :: "r"(saddr), "l"(g));
}
__device__ __forceinline__ void cp_commit() {
    asm volatile("cp.async.commit_group;");
}
__device__ __forceinline__ void cp_wait1() {
    asm volatile("cp.async.wait_group 1;");
}
__device__ __forceinline__ void ldm_x4(uint32_t& r0, uint32_t& r1, uint32_t& r2, uint32_t& r3,
                                       uint32_t addr) {
    asm volatile("ldmatrix.sync.aligned.m8n8.x4.shared.b16 {%0,%1,%2,%3}, [%4];"
                 : "=r"(r0), "=r"(r1), "=r"(r2), "=r"(r3) : "r"(addr));
}
__device__ __forceinline__ void mma16816(float* c, const uint32_t* a, const uint32_t* b) {
    asm volatile(
        "mma.sync.aligned.m16n8k16.row.col.f32.f16.f16.f32 "
        "{%0,%1,%2,%3}, {%4,%5,%6,%7}, {%8,%9}, {%0,%1,%2,%3};"
        : "+f"(c[0]), "+f"(c[1]), "+f"(c[2]), "+f"(c[3])
        : "r"(a[0]), "r"(a[1]), "r"(a[2]), "r"(a[3]), "r"(b[0]), "r"(b[1]));
}

/* ------------------------------------------------------------------ */
/* Conversion kernels                                                  */
/* ------------------------------------------------------------------ */
__global__ __launch_bounds__(256) void convert_x(const float* __restrict__ x)
{
    size_t i = ((size_t)blockIdx.x * 256 + threadIdx.x) * 4;
    float4 v = *(const float4*)(x + i);
    __half2* dst = (__half2*)(g_xh + i);
    dst[0] = __floats2half2_rn(v.x, v.y);
    dst[1] = __floats2half2_rn(v.z, v.w);
}

__global__ void convert_w(const float* __restrict__ Wi, const float* __restrict__ Wf,
                          const float* __restrict__ Wo, const float* __restrict__ Wz)
{
    const float* W = (blockIdx.z == 0) ? Wi : (blockIdx.z == 1) ? Wf
                   : (blockIdx.z == 2) ? Wo : Wz;
    __shared__ float t[32][33];
    int k0 = blockIdx.x * 32, n0 = blockIdx.y * 32;
    int tx = threadIdx.x, ty = threadIdx.y;    /* (32,8) */
#pragma unroll
    for (int j = 0; j < 4; j++)
        t[ty * 4 + j][tx] = W[(size_t)(k0 + ty * 4 + j) * DH + n0 + tx];
    __syncthreads();
#pragma unroll
    for (int j = 0; j < 4; j++) {
        float v = t[tx][ty * 4 + j];           /* k = k0+tx, n = n0+ty*4+j */
        size_t o = (size_t)(blockIdx.z * DH + n0 + ty * 4 + j) * DIN + k0 + tx;
        g_wt[o] = __float2half_rn(v);
    }
}

/* ------------------------------------------------------------------ */
/* HMMA GEMM, single-term fp16: v = x*W.                               */
/* BM=128 BN=128 BK=32, 8 warps (2x4), warp tile 64x32.                */
/* Stage = {A, B} for one 32-wide k-chunk; 2-buffer pipeline.          */
/* ------------------------------------------------------------------ */
#define LDS 40                          /* smem row stride in halves */
#define TILE_B (128 * LDS * 2)          /* 10240 B per operand tile */
#define STAGE_B (2 * TILE_B)            /* 20480 B per stage */
#define GEMM_SMEM (2 * STAGE_B)         /* 40960 B */
#define NKC 8                           /* 8 k-chunks of 32 */

__global__ __launch_bounds__(256) void gemm_hmma(
    const float* __restrict__ bi, const float* __restrict__ bfp,
    const float* __restrict__ bo, const float* __restrict__ bz)
{
    extern __shared__ __align__(16) char smem[];

    const int tid  = threadIdx.x;
    const int lane = tid & 31;
    const int w    = tid >> 5;
    const int wm   = w & 1;          /* warp m index (0..1)  -> 64 rows  */
    const int wn   = w >> 1;         /* warp n index (0..3)  -> 32 cols  */

    const int m0 = blockIdx.y * 128;
    const int n0 = blockIdx.x * 128; /* global concat-n */

    const uint32_t sb = smem_u32(smem);

    float acc[4][4][4];
#pragma unroll
    for (int i = 0; i < 4; i++)
#pragma unroll
        for (int j = 0; j < 4; j++)
#pragma unroll
            for (int e = 0; e < 4; e++) acc[i][j][e] = 0.f;

    /* ldmatrix lane address components */
    const uint32_t aRow = (lane & 15);
    const uint32_t aKof = (lane >> 4) * 8;
    const uint32_t bRow = (lane & 7) + ((lane >> 4) << 3);
    const uint32_t bKof = ((lane >> 3) & 1) * 8;

    /* cp.async mapping: per tile, thread covers rows tid>>2 and +64, k16=tid&3 */
    const int r0row = tid >> 2;
    const int k16   = tid & 3;
    const int r1row = r0row + 64;

    auto issue_stage = [&](int kc, int buf) {
        const int k0 = kc * 32;
        const __half* As = g_xh + (size_t)m0 * DIN;
        const __half* Bs = g_wt + (size_t)n0 * DIN;
        const uint32_t da = sb + buf * STAGE_B;
        const uint32_t db = da + TILE_B;
        const uint32_t so0 = (uint32_t)(r0row * LDS + k16 * 8) * 2;
        const uint32_t so1 = (uint32_t)(r1row * LDS + k16 * 8) * 2;
        cp_async16(da + so0, As + (size_t)r0row * DIN + k0 + k16 * 8);
        cp_async16(da + so1, As + (size_t)r1row * DIN + k0 + k16 * 8);
        cp_async16(db + so0, Bs + (size_t)r0row * DIN + k0 + k16 * 8);
        cp_async16(db + so1, Bs + (size_t)r1row * DIN + k0 + k16 * 8);
        cp_commit();
    };

    issue_stage(0, 0);
    issue_stage(1, 1);

#pragma unroll 1
    for (int kc = 0; kc < NKC; kc++) {
        cp_wait1();                 /* stage kc landed */
        __syncthreads();

        const uint32_t tA = sb + (kc & 1) * STAGE_B;
        const uint32_t tB = tA + TILE_B;

#pragma unroll
        for (int ks = 0; ks < 2; ks++) {
            const uint32_t kbase = ks * 16;
            uint32_t afr[4][4];
            uint32_t bfr[2][4];
#pragma unroll
            for (int q = 0; q < 2; q++) {
                uint32_t row = wn * 32 + q * 16 + bRow;
                ldm_x4(bfr[q][0], bfr[q][1], bfr[q][2], bfr[q][3],
                       tB + (row * LDS + kbase + bKof) * 2);
            }
#pragma unroll
            for (int i = 0; i < 4; i++) {
                uint32_t row = wm * 64 + i * 16 + aRow;
                ldm_x4(afr[i][0], afr[i][1], afr[i][2], afr[i][3],
                       tA + (row * LDS + kbase + aKof) * 2);
            }
#pragma unroll
            for (int i = 0; i < 4; i++)
#pragma unroll
                for (int j = 0; j < 4; j++)
                    mma16816(acc[i][j], afr[i], &bfr[j >> 1][(j & 1) * 2]);
        }

        __syncthreads();            /* compute done before buffer reuse */
        if (kc + 2 < NKC) issue_stage(kc + 2, kc & 1);
    }

    /* Epilogue: bias + activation, time-major gate write */
    const int gate = blockIdx.x >> 2;              /* 4 n-blocks per gate */
    const float* bias = (gate == 0) ? bi : (gate == 1) ? bfp : (gate == 2) ? bo : bz;
    float* outg = (gate == 0) ? g_gi : (gate == 1) ? g_gf : (gate == 2) ? g_go : g_gz;
    const int hblk = (blockIdx.x & 3) * 128;       /* h offset within gate */

#pragma unroll
    for (int i = 0; i < 4; i++) {
#pragma unroll
        for (int hh = 0; hh < 2; hh++) {
            int m = m0 + wm * 64 + i * 16 + (lane >> 2) + hh * 8;
            int b = m >> 12;
            int s = m & 4095;
            float* op = outg + (size_t)s * NCH + (size_t)b * DH;
#pragma unroll
            for (int j = 0; j < 4; j++) {
                int hcol = hblk + wn * 32 + j * 8 + (lane & 3) * 2;
                float v0 = acc[i][j][hh * 2 + 0] + bias[hcol + 0];
                float v1 = acc[i][j][hh * 2 + 1] + bias[hcol + 1];
                float r0, r1;
                if (gate <= 1) {
                    r0 = __expf(fminf(fmaxf(v0, -20.f), 0.f));
                    r1 = __expf(fminf(fmaxf(v1, -20.f), 0.f));
                } else if (gate == 2) {
                    r0 = 1.f / (1.f + __expf(-v0));
                    r1 = 1.f / (1.f + __expf(-v1));
                } else {
                    r0 = tanhf(v0);
                    r1 = tanhf(v1);
                }
                *(float2*)(op + hcol) = make_float2(r0, r1);
            }
        }
    }
}

/* ------------------------------------------------------------------ */
/* Scan (unchanged)                                                    */
/* ------------------------------------------------------------------ */
__global__ __launch_bounds__(128) void scan_passA()
{
    const int ch  = blockIdx.x * 128 + threadIdx.x;
    const int seg = blockIdx.y;
    const size_t off = (size_t)seg * TSEG * NCH + ch;
    const float* pf = g_gf + off;
    const float* pi = g_gi + off;
    const float* pz = g_gz + off;

    float A = 1.f, Bc = 0.f, Bn = 0.f;
#pragma unroll 1
    for (int t = 0; t < TSEG; t += 8) {
        float fv[8], iv[8], zv[8];
#pragma unroll
        for (int u = 0; u < 8; u++) {
            size_t idx = (size_t)(t + u) * NCH;
            fv[u] = pf[idx]; iv[u] = pi[idx]; zv[u] = pz[idx];
        }
#pragma unroll
        for (int u = 0; u < 8; u++) {
            Bc = fmaf(fv[u], Bc, iv[u] * zv[u]);
            Bn = fmaf(fv[u], Bn, iv[u]);
            A  = A * fv[u];
        }
    }
    g_A [(size_t)seg * NCH + ch] = A;
    g_Bc[(size_t)seg * NCH + ch] = Bc;
    g_Bn[(size_t)seg * NCH + ch] = Bn;
}

__global__ __launch_bounds__(128) void scan_passB()
{
    const int ch = blockIdx.x * 128 + threadIdx.x;
    float c = 0.f, n = 1.f;
#pragma unroll 1
    for (int sg = 0; sg < NSEG; sg++) {
        size_t idx = (size_t)sg * NCH + ch;
        g_Cs[idx] = c;
        g_Ns[idx] = n;
        float A  = g_A[idx];
        float Bc = g_Bc[idx];
        float Bn = g_Bn[idx];
        c = fmaf(A, c, Bc);
        n = fmaf(A, n, Bn);
    }
}

__global__ __launch_bounds__(128) void scan_passC(float* __restrict__ out)
{
    const int ch  = blockIdx.x * 128 + threadIdx.x;
    const int seg = blockIdx.y;
    const int b = ch >> 9;
    const int h = ch & 511;

    const size_t off = (size_t)seg * TSEG * NCH + ch;
    const float* pf = g_gf + off;
    const float* pi = g_gi + off;
    const float* po = g_go + off;
    const float* pz = g_gz + off;
    float* op = out + ((size_t)b * S_LEN + (size_t)seg * TSEG) * DH + h;

    size_t sidx = (size_t)seg * NCH + ch;
    float c = g_Cs[sidx];
    float n = g_Ns[sidx];

#pragma unroll 1
    for (int t = 0; t < TSEG; t += 8) {
        float fv[8], iv[8], ov[8], zv[8];
#pragma unroll
        for (int u = 0; u < 8; u++) {
            size_t idx = (size_t)(t + u) * NCH;
            fv[u] = pf[idx]; iv[u] = pi[idx]; ov[u] = po[idx]; zv[u] = pz[idx];
        }
#pragma unroll
        for (int u = 0; u < 8; u++) {
            c = fmaf(fv[u], c, iv[u] * zv[u]);
            n = fmaf(fv[u], n, iv[u]);
            op[(size_t)(t + u) * DH] = ov[u] * c / (n + 1e-6f);
        }
    }
}

/* ------------------------------------------------------------------ */
extern "C" void kernel_launch(void* const* d_in, const int* in_sizes, int n_in,
                              void* d_out, int out_size)
{
    const float* x  = (const float*)d_in[0];
    const float* Wi = (const float*)d_in[1];
    const float* bi = (const float*)d_in[2];
    const float* Wf = (const float*)d_in[3];
    const float* bf = (const float*)d_in[4];
    const float* Wo = (const float*)d_in[5];
    const float* bo = (const float*)d_in[6];
    const float* Wz = (const float*)d_in[7];
    const float* bz = (const float*)d_in[8];
    float* out = (float*)d_out;

    cudaFuncSetAttribute(gemm_hmma, cudaFuncAttributeMaxDynamicSharedMemorySize, GEMM_SMEM);

    convert_x<<<(MROWS * DIN / 4) / 256, 256>>>(x);
    convert_w<<<dim3(DIN / 32, DH / 32, 4), dim3(32, 8)>>>(Wi, Wf, Wo, Wz);

    gemm_hmma<<<dim3(NTOT / 128, MROWS / 128), 256, GEMM_SMEM>>>(bi, bf, bo, bz);

    dim3 gA(NCH / 128, NSEG);
    scan_passA<<<gA, 128>>>();
    scan_passB<<<NCH / 128, 128>>>();
    scan_passC<<<gA, 128>>>(out);
}